// round 4
// baseline (speedup 1.0000x reference)
#include <cuda_runtime.h>
#include <cstdint>

#define K_CLUST 256      // CLUST_SIZE
#define THREADS 256

__global__ __launch_bounds__(THREADS)
void clust_geo_edge_kernel(const float* __restrict__ data,     // [N_VOX, 5]
                           const int*   __restrict__ clusts,   // [N_CLUST, 256]
                           const int*   __restrict__ ei,       // [2, E]
                           float*       __restrict__ out,      // [E, 19]
                           int n_edge)
{
    const int e = blockIdx.x;
    const int t = threadIdx.x;

    // Shared staging: {x, y, z, 0.5*n} per voxel.
    // n mirrors XLA's padded xor-butterfly tree reduce over the size-3 row:
    //   lanes [x^2, y^2, z^2, 0]  ->  rn(rn(x^2+z^2) + y^2)
    __shared__ float4 s1[K_CLUST];
    __shared__ float4 s2[K_CLUST];
    __shared__ float  redv[THREADS];
    __shared__ int    redi[THREADS];

    const int c1 = ei[e];
    const int c2 = ei[n_edge + e];

    {
        int v1 = clusts[c1 * K_CLUST + t];
        const float* r = data + (size_t)v1 * 5;
        float x = r[0], y = r[1], z = r[2];
        float n = __fadd_rn(__fadd_rn(__fmul_rn(x, x), __fmul_rn(z, z)),
                            __fmul_rn(y, y));                     // pair02 tree
        s1[t] = make_float4(x, y, z, 0.5f * n);   // *0.5 exact

        int v2 = clusts[c2 * K_CLUST + t];
        const float* q = data + (size_t)v2 * 5;
        float X = q[0], Y = q[1], Z = q[2];
        float m = __fadd_rn(__fadd_rn(__fmul_rn(X, X), __fmul_rn(Z, Z)),
                            __fmul_rn(Y, Y));                     // pair02 tree
        s2[t] = make_float4(X, Y, Z, 0.5f * m);
    }
    __syncthreads();

    // Row i = t. Compare 0.5*d2 = (h1 + h2[j]) - c with c the GEMM-style
    // serial fma chain in k order:  c = fma(z1*z2, fma(y1*y2, rn(x1*x2))).
    // Exact 0.5 scaling keeps ordering AND tie structure bitwise identical
    // to the reference's d2 = (n1 + n2) - 2c.
    const float4 p = s1[t];
    float best  = __int_as_float(0x7f800000);     // +inf
    int   bestj = 0;

#pragma unroll 8
    for (int j = 0; j < K_CLUST; ++j) {
        float4 q = s2[j];                          // LDS.128 broadcast
        float c = __fmaf_rn(p.z, q.z,
                  __fmaf_rn(p.y, q.y,
                  __fmul_rn(p.x, q.x)));
        float d = __fsub_rn(__fadd_rn(p.w, q.w), c);
        // strict < + ascending j  ==> first occurrence wins within the row
        if (d < best) { best = d; bestj = j; }
    }

    redv[t] = best;
    redi[t] = (t << 8) | bestj;                    // flat index i*256 + j
    __syncthreads();

    // Tree reduction with first-occurrence (lowest flat index) tie-break.
#pragma unroll
    for (int s = THREADS / 2; s > 0; s >>= 1) {
        if (t < s) {
            float ov = redv[t + s];
            int   oi = redi[t + s];
            float mv = redv[t];
            int   mi = redi[t];
            if (ov < mv || (ov == mv && oi < mi)) {
                redv[t] = ov;
                redi[t] = oi;
            }
        }
        __syncthreads();
    }

    if (t == 0) {
        int flat = redi[0];
        int i1 = flat >> 8;
        int i2 = flat & 255;
        float4 a = s1[i1];
        float4 b = s2[i2];

        float dx = __fsub_rn(a.x, b.x);
        float dy = __fsub_rn(a.y, b.y);
        float dz = __fsub_rn(a.z, b.z);
        float lend = __fsqrt_rn(__fadd_rn(__fadd_rn(__fmul_rn(dx, dx),
                                                    __fmul_rn(dz, dz)),
                                          __fmul_rn(dy, dy)));
        float denom = (lend > 0.0f) ? lend : 1.0f;
        float ux = __fdiv_rn(dx, denom);
        float uy = __fdiv_rn(dy, denom);
        float uz = __fdiv_rn(dz, denom);

        float* o = out + (size_t)e * 19;
        o[0]  = a.x;  o[1]  = a.y;  o[2]  = a.z;     // v1
        o[3]  = b.x;  o[4]  = b.y;  o[5]  = b.z;     // v2
        o[6]  = ux;   o[7]  = uy;   o[8]  = uz;      // disp (normalized)
        o[9]  = lend;                                 // length
        o[10] = __fmul_rn(ux, ux); o[11] = __fmul_rn(ux, uy); o[12] = __fmul_rn(ux, uz);
        o[13] = __fmul_rn(uy, ux); o[14] = __fmul_rn(uy, uy); o[15] = __fmul_rn(uy, uz);
        o[16] = __fmul_rn(uz, ux); o[17] = __fmul_rn(uz, uy); o[18] = __fmul_rn(uz, uz);
    }
}

extern "C" void kernel_launch(void* const* d_in, const int* in_sizes, int n_in,
                              void* d_out, int out_size)
{
    const float* data   = (const float*)d_in[0];   // [N_VOX, 5] f32
    const int*   clusts = (const int*)  d_in[1];   // [N_CLUST, 256] i32
    const int*   ei     = (const int*)  d_in[2];   // [2, E] i32
    float*       out    = (float*)d_out;           // [E, 19] f32

    int n_edge = in_sizes[2] / 2;
    clust_geo_edge_kernel<<<n_edge, THREADS>>>(data, clusts, ei, out, n_edge);
}

// round 5
// speedup vs baseline: 1.2684x; 1.2684x over previous
#include <cuda_runtime.h>
#include <cstdint>

#define KC  256      // CLUST_SIZE
#define TPB 128      // threads per CTA; each thread owns rows 2t and 2t+1

typedef unsigned long long u64;

// ---- packed f32x2 helpers (Blackwell). Each lane rounds exactly like the
// ---- corresponding scalar .rn op, so results are bitwise identical. ----
__device__ __forceinline__ u64 pk2(float lo, float hi) {
    u64 r; asm("mov.b64 %0, {%1, %2};" : "=l"(r) : "f"(lo), "f"(hi)); return r;
}
__device__ __forceinline__ void upk2(u64 v, float& lo, float& hi) {
    asm("mov.b64 {%0, %1}, %2;" : "=f"(lo), "=f"(hi) : "l"(v));
}
__device__ __forceinline__ u64 mul2(u64 a, u64 b) {
    u64 r; asm("mul.rn.f32x2 %0, %1, %2;" : "=l"(r) : "l"(a), "l"(b)); return r;
}
__device__ __forceinline__ u64 add2(u64 a, u64 b) {
    u64 r; asm("add.rn.f32x2 %0, %1, %2;" : "=l"(r) : "l"(a), "l"(b)); return r;
}
__device__ __forceinline__ u64 fma2p(u64 a, u64 b, u64 c) {
    u64 r; asm("fma.rn.f32x2 %0, %1, %2, %3;" : "=l"(r) : "l"(a), "l"(b), "l"(c)); return r;
}

__global__ __launch_bounds__(TPB)
void clust_geo_edge_kernel(const float* __restrict__ data,     // [N_VOX, 5]
                           const int*   __restrict__ clusts,   // [N_CLUST, 256]
                           const int*   __restrict__ ei,       // [2, E]
                           float*       __restrict__ out,      // [E, 19]
                           int n_edge)
{
    __shared__ float4 s1[KC];        // cluster-1 rows: {x, y, z, h=0.5*n}
    __shared__ float4 sA[KC / 2];    // cluster-2 j-pairs: {x0, x1, y0, y1}
    __shared__ float4 sB[KC / 2];    // cluster-2 j-pairs: {z0, z1, h0, h1}
    __shared__ float  redv[TPB];
    __shared__ int    redi[TPB];

    const int e = blockIdx.x;
    const int t = threadIdx.x;
    const int c1 = ei[e];
    const int c2 = ei[n_edge + e];

    // ---- gather (arithmetic bit-identical to the passing round:
    //      n via pair02 tree  rn(rn(x^2+z^2)+y^2),  h = 0.5*n exact) ----
    float4 r0, r1;
    {
        int2 va = reinterpret_cast<const int2*>(clusts + c1 * KC)[t];
        const float* pa = data + (size_t)va.x * 5;
        const float* pb = data + (size_t)va.y * 5;
        float x = pa[0], y = pa[1], z = pa[2];
        float h = 0.5f * __fadd_rn(__fadd_rn(__fmul_rn(x, x), __fmul_rn(z, z)),
                                   __fmul_rn(y, y));
        r0 = make_float4(x, y, z, h);
        s1[2 * t] = r0;
        x = pb[0]; y = pb[1]; z = pb[2];
        h = 0.5f * __fadd_rn(__fadd_rn(__fmul_rn(x, x), __fmul_rn(z, z)),
                             __fmul_rn(y, y));
        r1 = make_float4(x, y, z, h);
        s1[2 * t + 1] = r1;

        int2 vb = reinterpret_cast<const int2*>(clusts + c2 * KC)[t];
        const float* qa = data + (size_t)vb.x * 5;
        const float* qb = data + (size_t)vb.y * 5;
        float X0 = qa[0], Y0 = qa[1], Z0 = qa[2];
        float H0 = 0.5f * __fadd_rn(__fadd_rn(__fmul_rn(X0, X0), __fmul_rn(Z0, Z0)),
                                    __fmul_rn(Y0, Y0));
        float X1 = qb[0], Y1 = qb[1], Z1 = qb[2];
        float H1 = 0.5f * __fadd_rn(__fadd_rn(__fmul_rn(X1, X1), __fmul_rn(Z1, Z1)),
                                    __fmul_rn(Y1, Y1));
        sA[t] = make_float4(X0, X1, Y0, Y1);
        sB[t] = make_float4(Z0, Z1, H0, H1);
    }
    __syncthreads();

    // Row constants, negated so the fma chain yields -c exactly
    // ( rn(-x) == -rn(x), so  d = (h1+h2) + (-c)  is bitwise  (h1+h2) - c ).
    const u64 nx0 = pk2(-r0.x, -r0.x), ny0 = pk2(-r0.y, -r0.y),
              nz0 = pk2(-r0.z, -r0.z), hh0 = pk2( r0.w,  r0.w);
    const u64 nx1 = pk2(-r1.x, -r1.x), ny1 = pk2(-r1.y, -r1.y),
              nz1 = pk2(-r1.z, -r1.z), hh1 = pk2( r1.w,  r1.w);

    const float INF = __int_as_float(0x7f800000);
    float best0 = INF, best1 = INF;
    int   bj0 = 0,     bj1 = 0;

#pragma unroll 2
    for (int kb = 0; kb < KC / 8; ++kb) {           // 8 j per block = 4 packed pairs
        float4 A0 = sA[kb * 4 + 0], B0 = sB[kb * 4 + 0];
        float4 A1 = sA[kb * 4 + 1], B1 = sB[kb * 4 + 1];
        float4 A2 = sA[kb * 4 + 2], B2 = sB[kb * 4 + 2];
        float4 A3 = sA[kb * 4 + 3], B3 = sB[kb * 4 + 3];

        u64 qx0 = pk2(A0.x, A0.y), qy0 = pk2(A0.z, A0.w), qz0 = pk2(B0.x, B0.y), qh0 = pk2(B0.z, B0.w);
        u64 qx1 = pk2(A1.x, A1.y), qy1 = pk2(A1.z, A1.w), qz1 = pk2(B1.x, B1.y), qh1 = pk2(B1.z, B1.w);
        u64 qx2 = pk2(A2.x, A2.y), qy2 = pk2(A2.z, A2.w), qz2 = pk2(B2.x, B2.y), qh2 = pk2(B2.z, B2.w);
        u64 qx3 = pk2(A3.x, A3.y), qy3 = pk2(A3.z, A3.w), qz3 = pk2(B3.x, B3.y), qh3 = pk2(B3.z, B3.w);

        // ---------------- row 0 ----------------
        {
            u64 d0 = add2(add2(hh0, qh0), fma2p(nz0, qz0, fma2p(ny0, qy0, mul2(nx0, qx0))));
            u64 d1 = add2(add2(hh0, qh1), fma2p(nz0, qz1, fma2p(ny0, qy1, mul2(nx0, qx1))));
            u64 d2 = add2(add2(hh0, qh2), fma2p(nz0, qz2, fma2p(ny0, qy2, mul2(nx0, qx2))));
            u64 d3 = add2(add2(hh0, qh3), fma2p(nz0, qz3, fma2p(ny0, qy3, mul2(nx0, qx3))));
            float a0, a1, b0, b1, c0, c1, e0, e1;
            upk2(d0, a0, a1); upk2(d1, b0, b1); upk2(d2, c0, c1); upk2(d3, e0, e1);
            float bm = fminf(fminf(fminf(a0, a1), fminf(b0, b1)),
                             fminf(fminf(c0, c1), fminf(e0, e1)));
            if (bm < best0) {                       // strict <: earlier block wins ties
                best0 = bm;
                int jb = kb * 8;                    // descending overwrite -> lowest j wins
                if (e1 == bm) bj0 = jb + 7;
                if (e0 == bm) bj0 = jb + 6;
                if (c1 == bm) bj0 = jb + 5;
                if (c0 == bm) bj0 = jb + 4;
                if (b1 == bm) bj0 = jb + 3;
                if (b0 == bm) bj0 = jb + 2;
                if (a1 == bm) bj0 = jb + 1;
                if (a0 == bm) bj0 = jb + 0;
            }
        }
        // ---------------- row 1 ----------------
        {
            u64 d0 = add2(add2(hh1, qh0), fma2p(nz1, qz0, fma2p(ny1, qy0, mul2(nx1, qx0))));
            u64 d1 = add2(add2(hh1, qh1), fma2p(nz1, qz1, fma2p(ny1, qy1, mul2(nx1, qx1))));
            u64 d2 = add2(add2(hh1, qh2), fma2p(nz1, qz2, fma2p(ny1, qy2, mul2(nx1, qx2))));
            u64 d3 = add2(add2(hh1, qh3), fma2p(nz1, qz3, fma2p(ny1, qy3, mul2(nx1, qx3))));
            float a0, a1, b0, b1, c0, c1, e0, e1;
            upk2(d0, a0, a1); upk2(d1, b0, b1); upk2(d2, c0, c1); upk2(d3, e0, e1);
            float bm = fminf(fminf(fminf(a0, a1), fminf(b0, b1)),
                             fminf(fminf(c0, c1), fminf(e0, e1)));
            if (bm < best1) {
                best1 = bm;
                int jb = kb * 8;
                if (e1 == bm) bj1 = jb + 7;
                if (e0 == bm) bj1 = jb + 6;
                if (c1 == bm) bj1 = jb + 5;
                if (c0 == bm) bj1 = jb + 4;
                if (b1 == bm) bj1 = jb + 3;
                if (b0 == bm) bj1 = jb + 2;
                if (a1 == bm) bj1 = jb + 1;
                if (a0 == bm) bj1 = jb + 0;
            }
        }
    }

    // Merge the two rows. Row 2t's flat indices are all smaller than row
    // 2t+1's, so strict < keeps first-occurrence semantics exactly.
    float bv;  int bf;
    if (best1 < best0) { bv = best1; bf = ((2 * t + 1) << 8) | bj1; }
    else               { bv = best0; bf = ((2 * t)     << 8) | bj0; }
    redv[t] = bv;
    redi[t] = bf;
    __syncthreads();

    // Tree reduction, lexicographic (value, flat index).
#pragma unroll
    for (int s = TPB / 2; s > 0; s >>= 1) {
        if (t < s) {
            float ov = redv[t + s];
            int   oi = redi[t + s];
            float mv = redv[t];
            int   mi = redi[t];
            if (ov < mv || (ov == mv && oi < mi)) {
                redv[t] = ov;
                redi[t] = oi;
            }
        }
        __syncthreads();
    }

    if (t == 0) {
        int flat = redi[0];
        int i1 = flat >> 8;
        int i2 = flat & 255;
        float4 a = s1[i1];
        float4 A = sA[i2 >> 1];
        float4 B = sB[i2 >> 1];
        int odd = i2 & 1;
        float bx = odd ? A.y : A.x;
        float by = odd ? A.w : A.z;
        float bz = odd ? B.y : B.x;

        float dx = __fsub_rn(a.x, bx);
        float dy = __fsub_rn(a.y, by);
        float dz = __fsub_rn(a.z, bz);
        float lend = __fsqrt_rn(__fadd_rn(__fadd_rn(__fmul_rn(dx, dx),
                                                    __fmul_rn(dz, dz)),
                                          __fmul_rn(dy, dy)));
        float denom = (lend > 0.0f) ? lend : 1.0f;
        float ux = __fdiv_rn(dx, denom);
        float uy = __fdiv_rn(dy, denom);
        float uz = __fdiv_rn(dz, denom);

        float* o = out + (size_t)e * 19;
        o[0]  = a.x; o[1]  = a.y; o[2]  = a.z;   // v1
        o[3]  = bx;  o[4]  = by;  o[5]  = bz;    // v2
        o[6]  = ux;  o[7]  = uy;  o[8]  = uz;    // disp
        o[9]  = lend;
        o[10] = __fmul_rn(ux, ux); o[11] = __fmul_rn(ux, uy); o[12] = __fmul_rn(ux, uz);
        o[13] = __fmul_rn(uy, ux); o[14] = __fmul_rn(uy, uy); o[15] = __fmul_rn(uy, uz);
        o[16] = __fmul_rn(uz, ux); o[17] = __fmul_rn(uz, uy); o[18] = __fmul_rn(uz, uz);
    }
}

extern "C" void kernel_launch(void* const* d_in, const int* in_sizes, int n_in,
                              void* d_out, int out_size)
{
    const float* data   = (const float*)d_in[0];   // [N_VOX, 5] f32
    const int*   clusts = (const int*)  d_in[1];   // [N_CLUST, 256] i32
    const int*   ei     = (const int*)  d_in[2];   // [2, E] i32
    float*       out    = (float*)d_out;           // [E, 19] f32

    int n_edge = in_sizes[2] / 2;
    clust_geo_edge_kernel<<<n_edge, TPB>>>(data, clusts, ei, out, n_edge);
}